// round 14
// baseline (speedup 1.0000x reference)
#include <cuda_runtime.h>

#define N_NODES 131072
#define NPER    4096
#define NBATCH  32
#define D       32
#define NREL    10
#define NG      14   // num_g_rels
#define SPLIT   16   // path sub-blocks per batch
#define OUT2_OFF (NBATCH * (NG + 1) * D)         // 15360
#define OUT3_OFF (OUT2_OFF + NBATCH * D)         // 16384

// ---------------- scratch (device globals; no allocation allowed) ----------------
__device__ __align__(16) float g_w1[N_NODES * D];
__device__ __align__(16) float g_U [N_NODES * D];    // indexed by COMPACT POSITION
__device__ __align__(16) float g_V [N_NODES * D];    // indexed by COMPACT POSITION
__device__ __align__(16) float g_S [N_NODES * 16];   // indexed by COMPACT POSITION
__device__ __align__(16) float g_nf[N_NODES * D];
__device__ int   g_pos[N_NODES];                 // node -> compact position (-1 inactive)
__device__ int   g_list[N_NODES];                // compact position -> node
__device__ int   g_cnt;                          // invariant: 0 at entry
__device__ float g_M1[D * D];     // (W2a - W2b) @ W_line
__device__ float g_M2[D * D];     // W2c @ W_line
__device__ float g_M3[D * D];     // self_loop_w @ W_line
__device__ float g_Cw[NREL * D];  // (attn_r @ (W2a+W2b) + b2) @ W_line
__device__ float g_pm[NBATCH * SPLIT];
__device__ float g_ps[NBATCH * SPLIT];
__device__ __align__(16) float g_pv[NBATCH * SPLIT * D];

__device__ __forceinline__ void red_add_v4(float* p, float4 v) {
    asm volatile("red.global.add.v4.f32 [%0], {%1,%2,%3,%4};"
                 :: "l"(p), "f"(v.x), "f"(v.y), "f"(v.z), "f"(v.w) : "memory");
}
__device__ __forceinline__ float fsel(const float4& q, int c) {
    return c == 0 ? q.x : (c == 1 ? q.y : (c == 2 ? q.z : q.w));
}

// ---------------- init: prep (block 0) + zero out + compaction/pos (+row zero) + w1 ----------------
__global__ void k_init(const float* __restrict__ feat, const float* __restrict__ Ww,
                       const float* __restrict__ bw,
                       const float* __restrict__ W2, const float* __restrict__ b2,
                       const float* __restrict__ attn, const float* __restrict__ SL,
                       const float* __restrict__ Wl,
                       float* __restrict__ out,
                       const int* __restrict__ idx1, const int* __restrict__ idx2,
                       const int* __restrict__ tar, int n_nodes) {
    if (blockIdx.x == 0) {
        __shared__ float Cs[NREL * D];
        int t = threadIdx.x;
        for (int i = t; i < NREL * D; i += blockDim.x) {
            int r = i / D, j = i % D;
            float acc = b2[j];
            #pragma unroll
            for (int k = 0; k < D; k++)
                acc += attn[r * D + k] * (W2[k * D + j] + W2[(D + k) * D + j]);
            Cs[i] = acc;
        }
        __syncthreads();
        for (int i = t; i < D * D; i += blockDim.x) {
            int k = i / D, d = i % D;
            float m1 = 0.f, m2 = 0.f, m3 = 0.f;
            #pragma unroll
            for (int j = 0; j < D; j++) {
                float wl = Wl[j * D + d];
                m1 += (W2[k * D + j] - W2[(D + k) * D + j]) * wl;
                m2 += W2[(2 * D + k) * D + j] * wl;
                m3 += SL[k * D + j] * wl;
            }
            g_M1[i] = m1; g_M2[i] = m2; g_M3[i] = m3;
        }
        for (int i = t; i < NREL * D; i += blockDim.x) {
            int r = i / D, d = i % D;
            float acc = 0.f;
            #pragma unroll
            for (int j = 0; j < D; j++) acc += Cs[r * D + j] * Wl[j * D + d];
            g_Cw[i] = acc;
        }
    }

    int tid = blockIdx.x * blockDim.x + threadIdx.x;
    int stride = gridDim.x * blockDim.x;
    if (tid < OUT3_OFF) out[tid] = 0.f;

    // compaction + position map + zero the claimed U/V/S rows (g_cnt == 0 at entry).
    // Positions within a warp are dense, so the zero-stores cover contiguous regions.
    {
        int n = tid;                              // stride >= n_nodes
        bool active = false;
        if (n < n_nodes)
            active = (__ldg(&idx1[n]) == 1) || (__ldg(&idx2[n]) != 0) || (__ldg(&tar[n]) == 1);
        unsigned m = __ballot_sync(0xffffffffu, active);
        int pos = -1;
        if (m) {
            int lane = threadIdx.x & 31;
            int rank = __popc(m & ((1u << lane) - 1u));
            int base = 0;
            if (lane == __ffs(m) - 1) base = atomicAdd(&g_cnt, __popc(m));
            base = __shfl_sync(0xffffffffu, base, __ffs(m) - 1);
            if (active) pos = base + rank;
        }
        if (n < n_nodes) g_pos[n] = pos;
        if (pos >= 0) {
            g_list[pos] = n;
            float4 z = make_float4(0.f, 0.f, 0.f, 0.f);
            float4* U4 = reinterpret_cast<float4*>(g_U) + pos * 8;
            float4* V4 = reinterpret_cast<float4*>(g_V) + pos * 8;
            float4* S4 = reinterpret_cast<float4*>(g_S) + pos * 4;
            #pragma unroll
            for (int j = 0; j < 8; j++) { U4[j] = z; V4[j] = z; }
            #pragma unroll
            for (int j = 0; j < 4; j++) S4[j] = z;
        }
    }

    // w1 = feat @ W_w + b_w : 16 nodes/warp
    __shared__ __align__(16) float Ws[D * D];
    for (int i = threadIdx.x; i < D * D; i += blockDim.x) Ws[i] = Ww[i];
    __syncthreads();
    const float4* Ws4 = reinterpret_cast<const float4*>(Ws);
    int lane = threadIdx.x & 31;
    int sub  = lane & 7;
    int grp  = lane >> 3;
    int warp = tid >> 5;
    int nw   = stride >> 5;
    float4 b4 = __ldg(reinterpret_cast<const float4*>(bw) + sub);
    for (int base = warp * 16; base < n_nodes; base += nw * 16) {
        float4 f4[4], acc[4];
        #pragma unroll
        for (int t = 0; t < 4; t++) {
            int n = base + grp * 4 + t;           // n_nodes % 16 == 0
            f4[t]  = *reinterpret_cast<const float4*>(&feat[n * D + sub * 4]);
            acc[t] = b4;
        }
        #pragma unroll
        for (int k = 0; k < D; k++) {
            float4 w = Ws4[k * 8 + sub];
            #pragma unroll
            for (int t = 0; t < 4; t++) {
                float fk = __shfl_sync(0xffffffffu, fsel(f4[t], k & 3), k >> 2, 8);
                acc[t].x += fk * w.x; acc[t].y += fk * w.y;
                acc[t].z += fk * w.z; acc[t].w += fk * w.w;
            }
        }
        #pragma unroll
        for (int t = 0; t < 4; t++) {
            int n = base + grp * 4 + t;
            *reinterpret_cast<float4*>(&g_w1[n * D + sub * 4]) = acc[t];
        }
    }
}

// ---------------- edge stage: 4 edges/warp, position-indexed accumulators ----------------
__global__ void k_edge(const int* __restrict__ src, const int* __restrict__ dst,
                       const int* __restrict__ ety, const float* __restrict__ norm,
                       const float* __restrict__ attn, int nE) {
    __shared__ float4 et_s[NREL * 8];
    for (int i = threadIdx.x; i < NREL * 8; i += blockDim.x)
        et_s[i] = reinterpret_cast<const float4*>(attn)[i];
    __syncthreads();
    int lane = threadIdx.x & 31;
    int sub  = lane & 7;
    int grp  = lane >> 3;
    int warp = (blockIdx.x * blockDim.x + threadIdx.x) >> 5;
    int nw   = (gridDim.x * blockDim.x) >> 5;
    for (int e0 = warp * 8; e0 < nE; e0 += nw * 8) {
        #pragma unroll
        for (int u = 0; u < 2; u++) {
            int e = e0 + u * 4 + grp;
            if (e >= nE) continue;
            int d = __ldg(&dst[e]);
            int p = __ldg(&g_pos[d]);
            if (p < 0) continue;                  // inactive dst: dead work
            int   s  = __ldg(&src[e]);
            int   r  = __ldg(&ety[e]);
            float nm = __ldg(&norm[e]);
            float4 f = *reinterpret_cast<const float4*>(&g_w1[s * D + sub * 4]);
            float4 t1 = make_float4(nm * f.x, nm * f.y, nm * f.z, nm * f.w);
            red_add_v4(&g_U[p * D + sub * 4], t1);
            float4 et = et_s[r * 8 + sub];
            float4 v  = make_float4(t1.x * et.x, t1.y * et.y, t1.z * et.z, t1.w * et.w);
            red_add_v4(&g_V[p * D + sub * 4], v);
            if (sub == 0) atomicAdd(&g_S[p * 16 + r], nm);
        }
    }
}

// ---------------- combine + scatter: U/V/S read SEQUENTIALLY by position ----------------
__global__ void __launch_bounds__(256, 2)
k_nf(const float* __restrict__ feat, const float* __restrict__ bline,
     const int* __restrict__ idx1, const int* __restrict__ idx2,
     const int* __restrict__ f2, const int* __restrict__ tar,
     float* __restrict__ out) {
    __shared__ __align__(16) float M1s[D * D], M2s[D * D], M3s[D * D], Cws[NREL * D];
    for (int i = threadIdx.x; i < D * D; i += blockDim.x) {
        M1s[i] = g_M1[i]; M2s[i] = g_M2[i]; M3s[i] = g_M3[i];
    }
    for (int i = threadIdx.x; i < NREL * D; i += blockDim.x) Cws[i] = g_Cw[i];
    __syncthreads();
    const float4* M14 = reinterpret_cast<const float4*>(M1s);
    const float4* M24 = reinterpret_cast<const float4*>(M2s);
    const float4* M34 = reinterpret_cast<const float4*>(M3s);
    const float4* Cw4 = reinterpret_cast<const float4*>(Cws);
    int cnt  = g_cnt;
    int lane = threadIdx.x & 31;
    int sub  = lane & 7;
    int grp  = lane >> 3;
    int warp = (blockIdx.x * blockDim.x + threadIdx.x) >> 5;
    int nw   = (gridDim.x * blockDim.x) >> 5;
    float4 b4 = __ldg(reinterpret_cast<const float4*>(bline) + sub);

    for (int base = warp * 16; base < cnt; base += nw * 16) {
        int  i_t[4], n_t[4];
        bool val_t[4];
        float4 acc[4];
        #pragma unroll
        for (int t = 0; t < 4; t++) {
            int i = base + grp * 4 + t;
            val_t[t] = i < cnt;
            i_t[t] = val_t[t] ? i : 0;
            n_t[t] = g_list[i_t[t]];
            acc[t] = b4;
        }
        {
            float sv0[4], sv1[4];
            #pragma unroll
            for (int t = 0; t < 4; t++) {
                sv0[t] = g_S[i_t[t] * 16 + sub];
                sv1[t] = g_S[i_t[t] * 16 + 8 + sub];
            }
            #pragma unroll
            for (int r = 0; r < NREL; r++) {
                float4 c = Cw4[r * 8 + sub];
                #pragma unroll
                for (int t = 0; t < 4; t++) {
                    float s_r = __shfl_sync(0xffffffffu, r < 8 ? sv0[t] : sv1[t], r & 7, 8);
                    acc[t].x += s_r * c.x; acc[t].y += s_r * c.y;
                    acc[t].z += s_r * c.z; acc[t].w += s_r * c.w;
                }
            }
        }
        {
            float4 u4[4], v4[4], f4[4];
            #pragma unroll
            for (int t = 0; t < 4; t++) {
                u4[t] = *reinterpret_cast<const float4*>(&g_U[i_t[t] * D + sub * 4]);
                v4[t] = *reinterpret_cast<const float4*>(&g_V[i_t[t] * D + sub * 4]);
                f4[t] = *reinterpret_cast<const float4*>(&feat[n_t[t] * D + sub * 4]);
            }
            #pragma unroll
            for (int k = 0; k < D; k++) {
                float4 m1 = M14[k * 8 + sub];
                float4 m2 = M24[k * 8 + sub];
                float4 m3 = M34[k * 8 + sub];
                #pragma unroll
                for (int t = 0; t < 4; t++) {
                    float uk = __shfl_sync(0xffffffffu, fsel(u4[t], k & 3), k >> 2, 8);
                    float vk = __shfl_sync(0xffffffffu, fsel(v4[t], k & 3), k >> 2, 8);
                    float fk = __shfl_sync(0xffffffffu, fsel(f4[t], k & 3), k >> 2, 8);
                    acc[t].x += uk * m1.x + vk * m2.x + fk * m3.x;
                    acc[t].y += uk * m1.y + vk * m2.y + fk * m3.y;
                    acc[t].z += uk * m1.z + vk * m2.z + fk * m3.z;
                    acc[t].w += uk * m1.w + vk * m2.w + fk * m3.w;
                }
            }
        }
        #pragma unroll
        for (int t = 0; t < 4; t++) {
            if (!val_t[t]) continue;
            int n = n_t[t];
            float4 val = make_float4(fmaxf(acc[t].x, 0.f), fmaxf(acc[t].y, 0.f),
                                     fmaxf(acc[t].z, 0.f), fmaxf(acc[t].w, 0.f));
            int b  = n >> 12;                     // n / NPER
            int i1 = __ldg(&idx1[n]);
            int i2 = __ldg(&idx2[n]);
            int tr = __ldg(&tar[n]);
            if (i1 == 1)
                *reinterpret_cast<float4*>(&g_nf[n * D + sub * 4]) = val;
            if (i2 != 0) {
                int slot = __ldg(&f2[n]) + 1;     // index_offset = 1
                if (slot <= NG)                   // slot NG+1 = dump row (dropped)
                    *reinterpret_cast<float4*>(&out[(b * (NG + 1) + slot) * D + sub * 4]) = val;
            }
            if (tr == 1)
                red_add_v4(&out[OUT2_OFF + b * D + sub * 4], val);
        }
    }
}

// ---------------- path softmax phase A: per-sub-block max/sum/partial (SPLIT=16, R=256) ----------------
__global__ void k_path1(const int* __restrict__ idx1, const float* __restrict__ out) {
    const int R = NPER / SPLIT;                   // 256 rows per block
    __shared__ float sc[R];
    __shared__ float tgt[D];
    __shared__ float red[8];
    __shared__ float wacc[8][D];
    int b = blockIdx.x / SPLIT, j = blockIdx.x % SPLIT;
    int t = threadIdx.x;
    int w = t >> 5, lane = t & 31;
    if (t < D) tgt[t] = out[OUT2_OFF + b * D + t];
    __syncthreads();
    size_t rbase = (size_t)b * NPER + (size_t)j * R;

    for (int i = t; i < R; i += 256) {
        float s = -1e30f;
        if (idx1[rbase + i] == 1) {
            const float4* row = reinterpret_cast<const float4*>(g_nf + (rbase + i) * D);
            float acc = 0.f;
            #pragma unroll
            for (int k = 0; k < 8; k++) {
                float4 r4 = row[k];
                acc += r4.x * tgt[k * 4 + 0] + r4.y * tgt[k * 4 + 1]
                     + r4.z * tgt[k * 4 + 2] + r4.w * tgt[k * 4 + 3];
            }
            s = acc;
        }
        sc[i] = s;
    }
    __syncthreads();

    float m = -1e30f;
    for (int i = t; i < R; i += 256) m = fmaxf(m, sc[i]);
    #pragma unroll
    for (int off = 16; off > 0; off >>= 1)
        m = fmaxf(m, __shfl_xor_sync(0xffffffffu, m, off));
    if (lane == 0) red[w] = m;
    __syncthreads();
    if (t < 8) {
        float mm = red[t];
        #pragma unroll
        for (int off = 4; off > 0; off >>= 1)
            mm = fmaxf(mm, __shfl_xor_sync(0xffu, mm, off));
        red[t] = mm;
    }
    __syncthreads();
    float mloc = red[0];
    __syncthreads();

    if (mloc < -1e29f) {                          // empty sub-block
        if (t == 0) { g_pm[blockIdx.x] = -1e30f; g_ps[blockIdx.x] = 0.f; }
        if (t < D) g_pv[blockIdx.x * D + t] = 0.f;
        return;
    }

    float ssum = 0.f;
    for (int i = t; i < R; i += 256) {
        float e = (sc[i] > -1e29f) ? __expf(sc[i] - mloc) : 0.f;
        sc[i] = e;
        ssum += e;
    }
    #pragma unroll
    for (int off = 16; off > 0; off >>= 1)
        ssum += __shfl_xor_sync(0xffffffffu, ssum, off);
    if (lane == 0) red[w] = ssum;
    __syncthreads();
    if (t < 8) {
        float s2 = red[t];
        #pragma unroll
        for (int off = 4; off > 0; off >>= 1)
            s2 += __shfl_xor_sync(0xffu, s2, off);
        red[t] = s2;
    }
    __syncthreads();
    float sloc = red[0];

    float a = 0.f;
    for (int i = w; i < R; i += 8) {
        float e = sc[i];
        if (e == 0.f) continue;
        a += e * g_nf[(rbase + i) * D + lane];
    }
    wacc[w][lane] = a;
    __syncthreads();
    if (t < D) {
        float acc = 0.f;
        #pragma unroll
        for (int q = 0; q < 8; q++) acc += wacc[q][t];
        g_pv[blockIdx.x * D + t] = acc;
    }
    if (t == 0) { g_pm[blockIdx.x] = mloc; g_ps[blockIdx.x] = sloc; }
}

// ---------------- path softmax phase B: combine + g_cnt reset ----------------
__global__ void k_path2(const float* __restrict__ zero_path, float* __restrict__ out) {
    int b = blockIdx.x, t = threadIdx.x;          // 32 threads
    if (b == 0 && t == 0) g_cnt = 0;              // restore invariant for next call
    float M = -1e30f;
    #pragma unroll
    for (int j = 0; j < SPLIT; j++) M = fmaxf(M, g_pm[b * SPLIT + j]);
    if (M < -1e29f) {
        out[OUT3_OFF + b * D + t] = zero_path[t];
        return;
    }
    float S = 0.f, v = 0.f;
    #pragma unroll
    for (int j = 0; j < SPLIT; j++) {
        float sc = __expf(g_pm[b * SPLIT + j] - M);
        S += sc * g_ps[b * SPLIT + j];
        v += sc * g_pv[(b * SPLIT + j) * D + t];
    }
    out[OUT3_OFF + b * D + t] = v / S;
}

// ---------------- launch ----------------
extern "C" void kernel_launch(void* const* d_in, const int* in_sizes, int n_in,
                              void* d_out, int out_size) {
    const float* feat = (const float*)d_in[0];
    const float* norm = (const float*)d_in[1];
    const float* W_w  = (const float*)d_in[2];
    const float* b_w  = (const float*)d_in[3];
    const float* W2   = (const float*)d_in[4];
    const float* b2   = (const float*)d_in[5];
    const float* attn = (const float*)d_in[6];
    const float* SL   = (const float*)d_in[7];
    const float* Wl   = (const float*)d_in[8];
    const float* bl   = (const float*)d_in[9];
    const float* zp   = (const float*)d_in[10];
    const int*   src  = (const int*)d_in[11];
    const int*   dst  = (const int*)d_in[12];
    const int*   ety  = (const int*)d_in[13];
    const int*   idx1 = (const int*)d_in[14];
    const int*   idx2 = (const int*)d_in[15];
    const int*   f2   = (const int*)d_in[16];
    const int*   tar  = (const int*)d_in[17];

    int nE     = in_sizes[11];
    int nNodes = in_sizes[0] / D;
    float* out = (float*)d_out;

    k_init<<<1184, 256>>>(feat, W_w, b_w, W2, b2, attn, SL, Wl, out,
                          idx1, idx2, tar, nNodes);
    k_edge<<<1184, 256>>>(src, dst, ety, norm, attn, nE);
    k_nf  <<<520, 256>>>(feat, bl, idx1, idx2, f2, tar, out);
    k_path1<<<NBATCH * SPLIT, 256>>>(idx1, out);
    k_path2<<<NBATCH, 32>>>(zp, out);
}

// round 15
// speedup vs baseline: 1.0156x; 1.0156x over previous
#include <cuda_runtime.h>

#define N_NODES 131072
#define NPER    4096
#define NBATCH  32
#define D       32
#define NREL    10
#define NG      14   // num_g_rels
#define SPLIT   16   // path sub-blocks per batch
#define OUT2_OFF (NBATCH * (NG + 1) * D)         // 15360
#define OUT3_OFF (OUT2_OFF + NBATCH * D)         // 16384

// ---------------- scratch (device globals; no allocation allowed) ----------------
__device__ __align__(16) float g_w1[N_NODES * D];
__device__ __align__(16) float g_U [N_NODES * D];    // indexed by COMPACT POSITION
__device__ __align__(16) float g_V [N_NODES * D];    // indexed by COMPACT POSITION
__device__ __align__(16) float g_S [N_NODES * 16];   // indexed by COMPACT POSITION
__device__ __align__(16) float g_nf[N_NODES * D];
__device__ int   g_pos[N_NODES];                 // node -> compact position (-1 inactive)
__device__ int   g_list[N_NODES];                // compact position -> node
__device__ int   g_cnt;                          // invariant: 0 at entry
__device__ float g_M1[D * D];     // (W2a - W2b) @ W_line
__device__ float g_M2[D * D];     // W2c @ W_line
__device__ float g_M3[D * D];     // self_loop_w @ W_line
__device__ float g_Cw[NREL * D];  // (attn_r @ (W2a+W2b) + b2) @ W_line
__device__ float g_pm[NBATCH * SPLIT];
__device__ float g_ps[NBATCH * SPLIT];
__device__ __align__(16) float g_pv[NBATCH * SPLIT * D];

__device__ __forceinline__ void red_add_v4(float* p, float4 v) {
    asm volatile("red.global.add.v4.f32 [%0], {%1,%2,%3,%4};"
                 :: "l"(p), "f"(v.x), "f"(v.y), "f"(v.z), "f"(v.w) : "memory");
}
__device__ __forceinline__ void red_add_v2(float* p, float2 v) {
    asm volatile("red.global.add.v2.f32 [%0], {%1,%2};"
                 :: "l"(p), "f"(v.x), "f"(v.y) : "memory");
}
__device__ __forceinline__ unsigned f2tf32(float x) {
    unsigned t;
    asm("cvt.rna.tf32.f32 %0, %1;" : "=r"(t) : "f"(x));
    return t;
}
__device__ __forceinline__ float fsel(const float4& q, int c) {
    return c == 0 ? q.x : (c == 1 ? q.y : (c == 2 ? q.z : q.w));
}

// ---------------- init: prep (block 0) + zero out + compaction/pos (+row zero) + w1 ----------------
__global__ void k_init(const float* __restrict__ feat, const float* __restrict__ Ww,
                       const float* __restrict__ bw,
                       const float* __restrict__ W2, const float* __restrict__ b2,
                       const float* __restrict__ attn, const float* __restrict__ SL,
                       const float* __restrict__ Wl,
                       float* __restrict__ out,
                       const int* __restrict__ idx1, const int* __restrict__ idx2,
                       const int* __restrict__ tar, int n_nodes) {
    if (blockIdx.x == 0) {
        __shared__ float Cs[NREL * D];
        int t = threadIdx.x;
        for (int i = t; i < NREL * D; i += blockDim.x) {
            int r = i / D, j = i % D;
            float acc = b2[j];
            #pragma unroll
            for (int k = 0; k < D; k++)
                acc += attn[r * D + k] * (W2[k * D + j] + W2[(D + k) * D + j]);
            Cs[i] = acc;
        }
        __syncthreads();
        for (int i = t; i < D * D; i += blockDim.x) {
            int k = i / D, d = i % D;
            float m1 = 0.f, m2 = 0.f, m3 = 0.f;
            #pragma unroll
            for (int j = 0; j < D; j++) {
                float wl = Wl[j * D + d];
                m1 += (W2[k * D + j] - W2[(D + k) * D + j]) * wl;
                m2 += W2[(2 * D + k) * D + j] * wl;
                m3 += SL[k * D + j] * wl;
            }
            g_M1[i] = m1; g_M2[i] = m2; g_M3[i] = m3;
        }
        for (int i = t; i < NREL * D; i += blockDim.x) {
            int r = i / D, d = i % D;
            float acc = 0.f;
            #pragma unroll
            for (int j = 0; j < D; j++) acc += Cs[r * D + j] * Wl[j * D + d];
            g_Cw[i] = acc;
        }
    }

    int tid = blockIdx.x * blockDim.x + threadIdx.x;
    int stride = gridDim.x * blockDim.x;
    if (tid < OUT3_OFF) out[tid] = 0.f;

    // compaction + position map + zero the claimed U/V/S rows (g_cnt == 0 at entry)
    {
        int n = tid;                              // stride >= n_nodes
        bool active = false;
        if (n < n_nodes)
            active = (__ldg(&idx1[n]) == 1) || (__ldg(&idx2[n]) != 0) || (__ldg(&tar[n]) == 1);
        unsigned m = __ballot_sync(0xffffffffu, active);
        int pos = -1;
        if (m) {
            int lane = threadIdx.x & 31;
            int rank = __popc(m & ((1u << lane) - 1u));
            int base = 0;
            if (lane == __ffs(m) - 1) base = atomicAdd(&g_cnt, __popc(m));
            base = __shfl_sync(0xffffffffu, base, __ffs(m) - 1);
            if (active) pos = base + rank;
        }
        if (n < n_nodes) g_pos[n] = pos;
        if (pos >= 0) {
            g_list[pos] = n;
            float4 z = make_float4(0.f, 0.f, 0.f, 0.f);
            float4* U4 = reinterpret_cast<float4*>(g_U) + pos * 8;
            float4* V4 = reinterpret_cast<float4*>(g_V) + pos * 8;
            float4* S4 = reinterpret_cast<float4*>(g_S) + pos * 4;
            #pragma unroll
            for (int j = 0; j < 8; j++) { U4[j] = z; V4[j] = z; }
            #pragma unroll
            for (int j = 0; j < 4; j++) S4[j] = z;
        }
    }

    // w1 = feat @ W_w + b_w : 16 nodes/warp
    __shared__ __align__(16) float Ws[D * D];
    for (int i = threadIdx.x; i < D * D; i += blockDim.x) Ws[i] = Ww[i];
    __syncthreads();
    const float4* Ws4 = reinterpret_cast<const float4*>(Ws);
    int lane = threadIdx.x & 31;
    int sub  = lane & 7;
    int grp  = lane >> 3;
    int warp = tid >> 5;
    int nw   = stride >> 5;
    float4 b4 = __ldg(reinterpret_cast<const float4*>(bw) + sub);
    for (int base = warp * 16; base < n_nodes; base += nw * 16) {
        float4 f4[4], acc[4];
        #pragma unroll
        for (int t = 0; t < 4; t++) {
            int n = base + grp * 4 + t;           // n_nodes % 16 == 0
            f4[t]  = *reinterpret_cast<const float4*>(&feat[n * D + sub * 4]);
            acc[t] = b4;
        }
        #pragma unroll
        for (int k = 0; k < D; k++) {
            float4 w = Ws4[k * 8 + sub];
            #pragma unroll
            for (int t = 0; t < 4; t++) {
                float fk = __shfl_sync(0xffffffffu, fsel(f4[t], k & 3), k >> 2, 8);
                acc[t].x += fk * w.x; acc[t].y += fk * w.y;
                acc[t].z += fk * w.z; acc[t].w += fk * w.w;
            }
        }
        #pragma unroll
        for (int t = 0; t < 4; t++) {
            int n = base + grp * 4 + t;
            *reinterpret_cast<float4*>(&g_w1[n * D + sub * 4]) = acc[t];
        }
    }
}

// ---------------- edge stage: 4 edges/warp, position-indexed accumulators ----------------
__global__ void k_edge(const int* __restrict__ src, const int* __restrict__ dst,
                       const int* __restrict__ ety, const float* __restrict__ norm,
                       const float* __restrict__ attn, int nE) {
    __shared__ float4 et_s[NREL * 8];
    for (int i = threadIdx.x; i < NREL * 8; i += blockDim.x)
        et_s[i] = reinterpret_cast<const float4*>(attn)[i];
    __syncthreads();
    int lane = threadIdx.x & 31;
    int sub  = lane & 7;
    int grp  = lane >> 3;
    int warp = (blockIdx.x * blockDim.x + threadIdx.x) >> 5;
    int nw   = (gridDim.x * blockDim.x) >> 5;
    for (int e0 = warp * 8; e0 < nE; e0 += nw * 8) {
        #pragma unroll
        for (int u = 0; u < 2; u++) {
            int e = e0 + u * 4 + grp;
            if (e >= nE) continue;
            int d = __ldg(&dst[e]);
            int p = __ldg(&g_pos[d]);
            if (p < 0) continue;                  // inactive dst: dead work
            int   s  = __ldg(&src[e]);
            int   r  = __ldg(&ety[e]);
            float nm = __ldg(&norm[e]);
            float4 f = *reinterpret_cast<const float4*>(&g_w1[s * D + sub * 4]);
            float4 t1 = make_float4(nm * f.x, nm * f.y, nm * f.z, nm * f.w);
            red_add_v4(&g_U[p * D + sub * 4], t1);
            float4 et = et_s[r * 8 + sub];
            float4 v  = make_float4(t1.x * et.x, t1.y * et.y, t1.z * et.z, t1.w * et.w);
            red_add_v4(&g_V[p * D + sub * 4], v);
            if (sub == 0) atomicAdd(&g_S[p * 16 + r], nm);
        }
    }
}

// ---------------- combine via tf32 mma.sync: nf = relu([U|V|feat|S] @ Mcat + b) ----------------
// X tile: 16 rows (compact positions) x K=112. Mcat: 112 x 32 (M1;M2;M3;Cw;0), tf32 in SMEM.
__global__ void __launch_bounds__(256)
k_nf(const float* __restrict__ feat, const float* __restrict__ bline,
     const int* __restrict__ idx1, const int* __restrict__ idx2,
     const int* __restrict__ f2, const int* __restrict__ tar,
     float* __restrict__ out) {
    // Mt[n][k] (transposed), stride 116 -> B-fragment LDS bank = (20*gid + tig) % 32: conflict-free
    __shared__ unsigned Mt[32 * 116];
    for (int i = threadIdx.x; i < 112 * 32; i += blockDim.x) {
        int k = i >> 5, d = i & 31;
        float v;
        if (k < 32)       v = g_M1[k * 32 + d];
        else if (k < 64)  v = g_M2[(k - 32) * 32 + d];
        else if (k < 96)  v = g_M3[(k - 64) * 32 + d];
        else if (k < 106) v = g_Cw[(k - 96) * 32 + d];
        else              v = 0.f;
        Mt[d * 116 + k] = f2tf32(v);
    }
    __syncthreads();

    int cnt = g_cnt;
    int ntiles = (cnt + 15) >> 4;
    int lane = threadIdx.x & 31;
    int gid  = lane >> 2;            // 0..7
    int tig  = lane & 3;             // 0..3
    int warp = (blockIdx.x * blockDim.x + threadIdx.x) >> 5;
    int nwarp = (gridDim.x * blockDim.x) >> 5;

    // per-lane output columns are fixed: col = nt*8 + tig*2 (+1)
    float2 bv[4];
    #pragma unroll
    for (int nt = 0; nt < 4; nt++)
        bv[nt] = *reinterpret_cast<const float2*>(&bline[nt * 8 + tig * 2]);

    for (int tile = warp; tile < ntiles; tile += nwarp) {
        int base = tile << 4;
        int r1 = gid, r2 = gid + 8;
        bool valid1 = (base + r1) < cnt;
        bool valid2 = (base + r2) < cnt;
        int p1 = valid1 ? base + r1 : cnt - 1;
        int p2 = valid2 ? base + r2 : cnt - 1;
        int n1 = g_list[p1];
        int n2 = g_list[p2];

        float c[4][4];
        #pragma unroll
        for (int nt = 0; nt < 4; nt++) {
            c[nt][0] = 0.f; c[nt][1] = 0.f; c[nt][2] = 0.f; c[nt][3] = 0.f;
        }

        #pragma unroll
        for (int kt = 0; kt < 14; kt++) {
            int off = (kt << 3) + tig;            // col in X (for a0/a1); a2/a3 at +4
            float a0f, a1f, a2f, a3f;
            if (kt < 4) {
                a0f = g_U[p1 * 32 + off];       a2f = g_U[p1 * 32 + off + 4];
                a1f = g_U[p2 * 32 + off];       a3f = g_U[p2 * 32 + off + 4];
            } else if (kt < 8) {
                int o = off - 32;
                a0f = g_V[p1 * 32 + o];         a2f = g_V[p1 * 32 + o + 4];
                a1f = g_V[p2 * 32 + o];         a3f = g_V[p2 * 32 + o + 4];
            } else if (kt < 12) {
                int o = off - 64;
                a0f = feat[n1 * 32 + o];        a2f = feat[n1 * 32 + o + 4];
                a1f = feat[n2 * 32 + o];        a3f = feat[n2 * 32 + o + 4];
            } else {
                int o = off - 96;
                a0f = g_S[p1 * 16 + o];         a2f = g_S[p1 * 16 + o + 4];
                a1f = g_S[p2 * 16 + o];         a3f = g_S[p2 * 16 + o + 4];
            }
            unsigned a0 = f2tf32(a0f), a1 = f2tf32(a1f);
            unsigned a2 = f2tf32(a2f), a3 = f2tf32(a3f);
            #pragma unroll
            for (int nt = 0; nt < 4; nt++) {
                unsigned b0 = Mt[(nt * 8 + gid) * 116 + (kt << 3) + tig];
                unsigned b1 = Mt[(nt * 8 + gid) * 116 + (kt << 3) + tig + 4];
                asm volatile(
                    "mma.sync.aligned.m16n8k8.row.col.f32.tf32.tf32.f32 "
                    "{%0,%1,%2,%3},{%4,%5,%6,%7},{%8,%9},{%0,%1,%2,%3};"
                    : "+f"(c[nt][0]), "+f"(c[nt][1]), "+f"(c[nt][2]), "+f"(c[nt][3])
                    : "r"(a0), "r"(a1), "r"(a2), "r"(a3), "r"(b0), "r"(b1));
            }
        }

        // epilogue: rows r1 (c[nt][0..1]) and r2 (c[nt][2..3]), cols nt*8 + tig*2 (+1)
        int i1a = __ldg(&idx1[n1]), i2a = __ldg(&idx2[n1]), tra = __ldg(&tar[n1]);
        int i1b = __ldg(&idx1[n2]), i2b = __ldg(&idx2[n2]), trb = __ldg(&tar[n2]);
        int slot1 = __ldg(&f2[n1]) + 1;
        int slot2 = __ldg(&f2[n2]) + 1;
        int b1 = n1 >> 12, b2 = n2 >> 12;
        #pragma unroll
        for (int nt = 0; nt < 4; nt++) {
            int col = nt * 8 + tig * 2;
            float2 v1 = make_float2(fmaxf(c[nt][0] + bv[nt].x, 0.f),
                                    fmaxf(c[nt][1] + bv[nt].y, 0.f));
            float2 v2 = make_float2(fmaxf(c[nt][2] + bv[nt].x, 0.f),
                                    fmaxf(c[nt][3] + bv[nt].y, 0.f));
            if (valid1) {
                if (i1a == 1)
                    *reinterpret_cast<float2*>(&g_nf[n1 * 32 + col]) = v1;
                if (i2a != 0 && slot1 <= NG)
                    *reinterpret_cast<float2*>(&out[(b1 * (NG + 1) + slot1) * 32 + col]) = v1;
                if (tra == 1)
                    red_add_v2(&out[OUT2_OFF + b1 * 32 + col], v1);
            }
            if (valid2) {
                if (i1b == 1)
                    *reinterpret_cast<float2*>(&g_nf[n2 * 32 + col]) = v2;
                if (i2b != 0 && slot2 <= NG)
                    *reinterpret_cast<float2*>(&out[(b2 * (NG + 1) + slot2) * 32 + col]) = v2;
                if (trb == 1)
                    red_add_v2(&out[OUT2_OFF + b2 * 32 + col], v2);
            }
        }
    }
}

// ---------------- path softmax phase A: per-sub-block max/sum/partial (SPLIT=16, R=256) ----------------
__global__ void k_path1(const int* __restrict__ idx1, const float* __restrict__ out) {
    const int R = NPER / SPLIT;                   // 256 rows per block
    __shared__ float sc[R];
    __shared__ float tgt[D];
    __shared__ float red[8];
    __shared__ float wacc[8][D];
    int b = blockIdx.x / SPLIT, j = blockIdx.x % SPLIT;
    int t = threadIdx.x;
    int w = t >> 5, lane = t & 31;
    if (t < D) tgt[t] = out[OUT2_OFF + b * D + t];
    __syncthreads();
    size_t rbase = (size_t)b * NPER + (size_t)j * R;

    for (int i = t; i < R; i += 256) {
        float s = -1e30f;
        if (idx1[rbase + i] == 1) {
            const float4* row = reinterpret_cast<const float4*>(g_nf + (rbase + i) * D);
            float acc = 0.f;
            #pragma unroll
            for (int k = 0; k < 8; k++) {
                float4 r4 = row[k];
                acc += r4.x * tgt[k * 4 + 0] + r4.y * tgt[k * 4 + 1]
                     + r4.z * tgt[k * 4 + 2] + r4.w * tgt[k * 4 + 3];
            }
            s = acc;
        }
        sc[i] = s;
    }
    __syncthreads();

    float m = -1e30f;
    for (int i = t; i < R; i += 256) m = fmaxf(m, sc[i]);
    #pragma unroll
    for (int off = 16; off > 0; off >>= 1)
        m = fmaxf(m, __shfl_xor_sync(0xffffffffu, m, off));
    if (lane == 0) red[w] = m;
    __syncthreads();
    if (t < 8) {
        float mm = red[t];
        #pragma unroll
        for (int off = 4; off > 0; off >>= 1)
            mm = fmaxf(mm, __shfl_xor_sync(0xffu, mm, off));
        red[t] = mm;
    }
    __syncthreads();
    float mloc = red[0];
    __syncthreads();

    if (mloc < -1e29f) {                          // empty sub-block
        if (t == 0) { g_pm[blockIdx.x] = -1e30f; g_ps[blockIdx.x] = 0.f; }
        if (t < D) g_pv[blockIdx.x * D + t] = 0.f;
        return;
    }

    float ssum = 0.f;
    for (int i = t; i < R; i += 256) {
        float e = (sc[i] > -1e29f) ? __expf(sc[i] - mloc) : 0.f;
        sc[i] = e;
        ssum += e;
    }
    #pragma unroll
    for (int off = 16; off > 0; off >>= 1)
        ssum += __shfl_xor_sync(0xffffffffu, ssum, off);
    if (lane == 0) red[w] = ssum;
    __syncthreads();
    if (t < 8) {
        float s2 = red[t];
        #pragma unroll
        for (int off = 4; off > 0; off >>= 1)
            s2 += __shfl_xor_sync(0xffu, s2, off);
        red[t] = s2;
    }
    __syncthreads();
    float sloc = red[0];

    float a = 0.f;
    for (int i = w; i < R; i += 8) {
        float e = sc[i];
        if (e == 0.f) continue;
        a += e * g_nf[(rbase + i) * D + lane];
    }
    wacc[w][lane] = a;
    __syncthreads();
    if (t < D) {
        float acc = 0.f;
        #pragma unroll
        for (int q = 0; q < 8; q++) acc += wacc[q][t];
        g_pv[blockIdx.x * D + t] = acc;
    }
    if (t == 0) { g_pm[blockIdx.x] = mloc; g_ps[blockIdx.x] = sloc; }
}

// ---------------- path softmax phase B: combine + g_cnt reset ----------------
__global__ void k_path2(const float* __restrict__ zero_path, float* __restrict__ out) {
    int b = blockIdx.x, t = threadIdx.x;          // 32 threads
    if (b == 0 && t == 0) g_cnt = 0;              // restore invariant for next call
    float M = -1e30f;
    #pragma unroll
    for (int j = 0; j < SPLIT; j++) M = fmaxf(M, g_pm[b * SPLIT + j]);
    if (M < -1e29f) {
        out[OUT3_OFF + b * D + t] = zero_path[t];
        return;
    }
    float S = 0.f, v = 0.f;
    #pragma unroll
    for (int j = 0; j < SPLIT; j++) {
        float sc = __expf(g_pm[b * SPLIT + j] - M);
        S += sc * g_ps[b * SPLIT + j];
        v += sc * g_pv[(b * SPLIT + j) * D + t];
    }
    out[OUT3_OFF + b * D + t] = v / S;
}

// ---------------- launch ----------------
extern "C" void kernel_launch(void* const* d_in, const int* in_sizes, int n_in,
                              void* d_out, int out_size) {
    const float* feat = (const float*)d_in[0];
    const float* norm = (const float*)d_in[1];
    const float* W_w  = (const float*)d_in[2];
    const float* b_w  = (const float*)d_in[3];
    const float* W2   = (const float*)d_in[4];
    const float* b2   = (const float*)d_in[5];
    const float* attn = (const float*)d_in[6];
    const float* SL   = (const float*)d_in[7];
    const float* Wl   = (const float*)d_in[8];
    const float* bl   = (const float*)d_in[9];
    const float* zp   = (const float*)d_in[10];
    const int*   src  = (const int*)d_in[11];
    const int*   dst  = (const int*)d_in[12];
    const int*   ety  = (const int*)d_in[13];
    const int*   idx1 = (const int*)d_in[14];
    const int*   idx2 = (const int*)d_in[15];
    const int*   f2   = (const int*)d_in[16];
    const int*   tar  = (const int*)d_in[17];

    int nE     = in_sizes[11];
    int nNodes = in_sizes[0] / D;
    float* out = (float*)d_out;

    k_init<<<1184, 256>>>(feat, W_w, b_w, W2, b2, attn, SL, Wl, out,
                          idx1, idx2, tar, nNodes);
    k_edge<<<1184, 256>>>(src, dst, ety, norm, attn, nE);
    k_nf  <<<520, 256>>>(feat, bl, idx1, idx2, f2, tar, out);
    k_path1<<<NBATCH * SPLIT, 256>>>(idx1, out);
    k_path2<<<NBATCH, 32>>>(zp, out);
}